// round 1
// baseline (speedup 1.0000x reference)
#include <cuda_runtime.h>
#include <cuda_bf16.h>
#include <math_constants.h>

// Problem constants
#define N_NODES   50000
#define N_EDGES   800000
#define IN_FEATS  256
#define EDGE_FEATS 64
#define NUM_HEADS 4
#define OUT_FEATS 32
#define HF        128           // NUM_HEADS*OUT_FEATS
#define QCOLS     256           // NUM_HEADS*EDGE_FEATS

// Scratch (static device globals; no allocation allowed)
__device__ float g_h[N_NODES * HF];          // projected node feats  [N,128]
__device__ float g_q[N_NODES * QCOLS];       // q[n,h,k]              [N,4,64] (pre-scaled by 1/sqrt(32))
__device__ float g_sc[N_EDGES * NUM_HEADS];  // score, then exp(score-max) in-place
__device__ float g_smax[N_NODES * NUM_HEADS];
__device__ float g_den[N_NODES * NUM_HEADS];

// ---------------------------------------------------------------------------
// init: zero d_out + den, set smax = -inf
// ---------------------------------------------------------------------------
__global__ void init_kernel(float* __restrict__ out) {
    int i = blockIdx.x * blockDim.x + threadIdx.x;
    int stride = gridDim.x * blockDim.x;
    for (int j = i; j < N_NODES * HF; j += stride) out[j] = 0.0f;
    for (int j = i; j < N_NODES * NUM_HEADS; j += stride) {
        g_smax[j] = -CUDART_INF_F;
        g_den[j]  = 0.0f;
    }
}

// ---------------------------------------------------------------------------
// K1: h = node_feat[N,256] @ W_node[256,128]  (register-blocked SGEMM)
// BM=64, BN=128, BK=32, 256 threads, 8x4 microtile
// ---------------------------------------------------------------------------
__global__ __launch_bounds__(256) void gemm_node_kernel(
    const float* __restrict__ A, const float* __restrict__ B) {
    __shared__ float As[32][64];   // transposed A tile: As[k][m]
    __shared__ float Bs[32][128];

    const int tid = threadIdx.x;
    const int block_m = blockIdx.x * 64;
    const int tcol = (tid & 31) * 4;   // 0..124
    const int trow = (tid >> 5) * 8;   // 0..56

    float acc[8][4];
#pragma unroll
    for (int i = 0; i < 8; i++)
#pragma unroll
        for (int j = 0; j < 4; j++) acc[i][j] = 0.0f;

    for (int k0 = 0; k0 < IN_FEATS; k0 += 32) {
        // A tile: 64x32 floats = 512 float4, 2 per thread, store transposed
#pragma unroll
        for (int i = 0; i < 2; i++) {
            int idx = tid + i * 256;          // 0..511
            int row = idx >> 3;               // 0..63
            int kk  = (idx & 7) * 4;          // 0..28
            float4 v = make_float4(0.f, 0.f, 0.f, 0.f);
            int grow = block_m + row;
            if (grow < N_NODES)
                v = *(const float4*)&A[grow * IN_FEATS + k0 + kk];
            As[kk + 0][row] = v.x; As[kk + 1][row] = v.y;
            As[kk + 2][row] = v.z; As[kk + 3][row] = v.w;
        }
        // B tile: 32x128 = 1024 float4, 4 per thread
#pragma unroll
        for (int i = 0; i < 4; i++) {
            int idx = tid + i * 256;          // 0..1023
            int row = idx >> 5;               // 0..31
            int cc  = (idx & 31) * 4;
            *(float4*)&Bs[row][cc] = *(const float4*)&B[(k0 + row) * HF + cc];
        }
        __syncthreads();

#pragma unroll
        for (int kk = 0; kk < 32; kk++) {
            float a[8];
#pragma unroll
            for (int i = 0; i < 8; i++) a[i] = As[kk][trow + i];
            float4 bv = *(float4*)&Bs[kk][tcol];
#pragma unroll
            for (int i = 0; i < 8; i++) {
                acc[i][0] += a[i] * bv.x;
                acc[i][1] += a[i] * bv.y;
                acc[i][2] += a[i] * bv.z;
                acc[i][3] += a[i] * bv.w;
            }
        }
        __syncthreads();
    }

#pragma unroll
    for (int i = 0; i < 8; i++) {
        int grow = block_m + trow + i;
        if (grow < N_NODES) {
            float4 v = make_float4(acc[i][0], acc[i][1], acc[i][2], acc[i][3]);
            *(float4*)&g_h[grow * HF + tcol] = v;
        }
    }
}

// ---------------------------------------------------------------------------
// K2: q[n,h,k] = (1/sqrt(32)) * sum_f h[n,h*32+f] * W_edge[k, h*32+f]
// Block: 256 threads (thread = (h,k)), 16 nodes per block in groups of 4.
// ---------------------------------------------------------------------------
__global__ __launch_bounds__(256) void make_q_kernel(const float* __restrict__ We) {
    __shared__ float WeT[HF * EDGE_FEATS];   // WeT[c*64 + k] = We[k*128 + c], 32KB
    __shared__ float hs[4][HF];

    const int tid = threadIdx.x;
    for (int i = tid; i < EDGE_FEATS * HF; i += 256) {
        int k = i >> 7, c = i & 127;
        WeT[c * EDGE_FEATS + k] = We[i];
    }

    const int hh = tid >> 6;        // head 0..3
    const int k  = tid & 63;        // 0..63
    const int node0 = blockIdx.x * 16;
    const float scale = 0.17677669529663687f;   // 1/sqrt(32)

    for (int g = 0; g < 4; g++) {
        __syncthreads();
        for (int i = tid; i < 4 * HF; i += 256) {
            int ni = i >> 7, c = i & 127;
            int n = node0 + g * 4 + ni;
            hs[ni][c] = (n < N_NODES) ? g_h[n * HF + c] : 0.0f;
        }
        __syncthreads();

        float acc[4] = {0.f, 0.f, 0.f, 0.f};
#pragma unroll
        for (int f = 0; f < OUT_FEATS; f++) {
            float w = WeT[(hh * OUT_FEATS + f) * EDGE_FEATS + k];
#pragma unroll
            for (int ni = 0; ni < 4; ni++) acc[ni] += hs[ni][hh * OUT_FEATS + f] * w;
        }
#pragma unroll
        for (int ni = 0; ni < 4; ni++) {
            int n = node0 + g * 4 + ni;
            if (n < N_NODES)
                g_q[(n * NUM_HEADS + hh) * EDGE_FEATS + k] = acc[ni] * scale;
        }
    }
}

// ---------------------------------------------------------------------------
// atomic max on float via int-ordering trick (stored bits are real float bits)
// ---------------------------------------------------------------------------
__device__ __forceinline__ void atomicMaxF(float* addr, float v) {
    if (v >= 0.0f) atomicMax((int*)addr, __float_as_int(v));
    else           atomicMin((unsigned int*)addr, __float_as_uint(v));
}

// ---------------------------------------------------------------------------
// K3: warp per edge. score[e,h] = leaky(sum_k ef[e,k]*q[src,h,k]); seg-max.
// ---------------------------------------------------------------------------
__global__ __launch_bounds__(256) void score_kernel(
    const float* __restrict__ ef, const int* __restrict__ src,
    const int* __restrict__ dst) {
    int e = (blockIdx.x * 256 + threadIdx.x) >> 5;
    if (e >= N_EDGES) return;
    int lane = threadIdx.x & 31;

    int s = src[e];
    float e0 = ef[e * EDGE_FEATS + lane];
    float e1 = ef[e * EDGE_FEATS + 32 + lane];
    const float* qs = g_q + s * QCOLS;

    float sc[4];
#pragma unroll
    for (int h = 0; h < NUM_HEADS; h++) {
        float p = e0 * qs[h * EDGE_FEATS + lane] + e1 * qs[h * EDGE_FEATS + 32 + lane];
#pragma unroll
        for (int o = 16; o > 0; o >>= 1) p += __shfl_xor_sync(0xffffffffu, p, o);
        sc[h] = p;
    }
    if (lane < NUM_HEADS) {
        float v = sc[lane];
        v = (v > 0.0f) ? v : 0.01f * v;          // leaky relu, slope 0.01
        g_sc[e * NUM_HEADS + lane] = v;
        int d = dst[e];
        atomicMaxF(&g_smax[d * NUM_HEADS + lane], v);
    }
}

// ---------------------------------------------------------------------------
// K4: a = exp(score - smax[dst]); denom segment sum. In-place into g_sc.
// ---------------------------------------------------------------------------
__global__ __launch_bounds__(256) void exp_kernel(const int* __restrict__ dst) {
    int i = blockIdx.x * 256 + threadIdx.x;
    if (i >= N_EDGES * NUM_HEADS) return;
    int e = i >> 2, h = i & 3;
    int d = dst[e];
    float v = __expf(g_sc[i] - g_smax[d * NUM_HEADS + h]);
    g_sc[i] = v;
    atomicAdd(&g_den[d * NUM_HEADS + h], v);
}

// ---------------------------------------------------------------------------
// vector reduction (16B) to global — sm_90+
// ---------------------------------------------------------------------------
__device__ __forceinline__ void redAdd4(float* p, float4 v) {
    asm volatile("red.global.add.v4.f32 [%0], {%1, %2, %3, %4};"
                 :: "l"(p), "f"(v.x), "f"(v.y), "f"(v.z), "f"(v.w) : "memory");
}

// ---------------------------------------------------------------------------
// K5: warp per edge. out[dst] += h[src] * attn  (attn = a/denom[dst])
// lane l covers features [4l, 4l+4); head = l>>3.
// ---------------------------------------------------------------------------
__global__ __launch_bounds__(256) void agg_kernel(
    const int* __restrict__ src, const int* __restrict__ dst,
    float* __restrict__ out) {
    int e = (blockIdx.x * 256 + threadIdx.x) >> 5;
    if (e >= N_EDGES) return;
    int lane = threadIdx.x & 31;
    int hh = lane >> 3;

    int s = src[e];
    int d = dst[e];
    float attn = g_sc[e * NUM_HEADS + hh] / g_den[d * NUM_HEADS + hh];

    float4 hv = *(const float4*)&g_h[s * HF + lane * 4];
    float4 m = make_float4(hv.x * attn, hv.y * attn, hv.z * attn, hv.w * attn);
    redAdd4(&out[d * HF + lane * 4], m);
}

// ---------------------------------------------------------------------------
extern "C" void kernel_launch(void* const* d_in, const int* in_sizes, int n_in,
                              void* d_out, int out_size) {
    const float* node_feat = (const float*)d_in[0];
    const float* edge_feat = (const float*)d_in[1];
    const int*   src       = (const int*)d_in[2];
    const int*   dst       = (const int*)d_in[3];
    const float* W_node    = (const float*)d_in[4];
    const float* W_edge    = (const float*)d_in[5];
    float* out = (float*)d_out;

    init_kernel<<<2048, 256>>>(out);
    gemm_node_kernel<<<(N_NODES + 63) / 64, 256>>>(node_feat, W_node);
    make_q_kernel<<<(N_NODES + 15) / 16, 256>>>(W_edge);
    score_kernel<<<(N_EDGES * 32 + 255) / 256, 256>>>(edge_feat, src, dst);
    exp_kernel<<<(N_EDGES * NUM_HEADS + 255) / 256, 256>>>(dst);
    agg_kernel<<<(N_EDGES * 32 + 255) / 256, 256>>>(src, dst, out);
}

// round 2
// speedup vs baseline: 1.1947x; 1.1947x over previous
#include <cuda_runtime.h>
#include <cuda_bf16.h>
#include <math_constants.h>

// Problem constants
#define N_NODES   50000
#define N_EDGES   800000
#define IN_FEATS  256
#define EDGE_FEATS 64
#define NUM_HEADS 4
#define OUT_FEATS 32
#define HF        128           // NUM_HEADS*OUT_FEATS
#define QCOLS     256           // NUM_HEADS*EDGE_FEATS

#define SCAN_BLK  512
#define NB_SCAN   ((N_NODES + SCAN_BLK - 1) / SCAN_BLK)   // 98

// Scratch (static device globals; no allocation allowed)
__device__ float g_h[N_NODES * HF];          // projected node feats  [N,128]
__device__ float g_q[N_NODES * QCOLS];       // q[n,h,k]  [N,4,64]  pre-scaled by 1/sqrt(32)
__device__ int   g_cnt[N_NODES];             // in-degree histogram
__device__ int   g_off[N_NODES + 1];         // CSR offsets (by dst)
__device__ int   g_cur[N_NODES];             // scatter cursors
__device__ int   g_eid[N_EDGES];             // edge ids grouped by dst
__device__ int   g_part[NB_SCAN];            // scan block sums
__device__ int   g_partx[NB_SCAN];           // scan block prefix (exclusive)

// ---------------------------------------------------------------------------
// zero histogram
// ---------------------------------------------------------------------------
__global__ void zero_cnt_kernel() {
    int i = blockIdx.x * blockDim.x + threadIdx.x;
    if (i < N_NODES) g_cnt[i] = 0;
}

// ---------------------------------------------------------------------------
// K1: h = node_feat[N,256] @ W_node[256,128]  (register-blocked SGEMM)
// ---------------------------------------------------------------------------
__global__ __launch_bounds__(256) void gemm_node_kernel(
    const float* __restrict__ A, const float* __restrict__ B) {
    __shared__ float As[32][64];   // transposed A tile: As[k][m]
    __shared__ float Bs[32][128];

    const int tid = threadIdx.x;
    const int block_m = blockIdx.x * 64;
    const int tcol = (tid & 31) * 4;
    const int trow = (tid >> 5) * 8;

    float acc[8][4];
#pragma unroll
    for (int i = 0; i < 8; i++)
#pragma unroll
        for (int j = 0; j < 4; j++) acc[i][j] = 0.0f;

    for (int k0 = 0; k0 < IN_FEATS; k0 += 32) {
#pragma unroll
        for (int i = 0; i < 2; i++) {
            int idx = tid + i * 256;
            int row = idx >> 3;
            int kk  = (idx & 7) * 4;
            float4 v = make_float4(0.f, 0.f, 0.f, 0.f);
            int grow = block_m + row;
            if (grow < N_NODES)
                v = *(const float4*)&A[grow * IN_FEATS + k0 + kk];
            As[kk + 0][row] = v.x; As[kk + 1][row] = v.y;
            As[kk + 2][row] = v.z; As[kk + 3][row] = v.w;
        }
#pragma unroll
        for (int i = 0; i < 4; i++) {
            int idx = tid + i * 256;
            int row = idx >> 5;
            int cc  = (idx & 31) * 4;
            *(float4*)&Bs[row][cc] = *(const float4*)&B[(k0 + row) * HF + cc];
        }
        __syncthreads();

#pragma unroll
        for (int kk = 0; kk < 32; kk++) {
            float a[8];
#pragma unroll
            for (int i = 0; i < 8; i++) a[i] = As[kk][trow + i];
            float4 bv = *(float4*)&Bs[kk][tcol];
#pragma unroll
            for (int i = 0; i < 8; i++) {
                acc[i][0] += a[i] * bv.x;
                acc[i][1] += a[i] * bv.y;
                acc[i][2] += a[i] * bv.z;
                acc[i][3] += a[i] * bv.w;
            }
        }
        __syncthreads();
    }

#pragma unroll
    for (int i = 0; i < 8; i++) {
        int grow = block_m + trow + i;
        if (grow < N_NODES) {
            float4 v = make_float4(acc[i][0], acc[i][1], acc[i][2], acc[i][3]);
            *(float4*)&g_h[grow * HF + tcol] = v;
        }
    }
}

// ---------------------------------------------------------------------------
// K2: q[n,h,k] = (1/sqrt(32)) * sum_f h[n,h*32+f] * W_edge[k, h*32+f]
// ---------------------------------------------------------------------------
__global__ __launch_bounds__(256) void make_q_kernel(const float* __restrict__ We) {
    __shared__ float WeT[HF * EDGE_FEATS];   // WeT[c*64 + k] = We[k*128 + c]
    __shared__ float hs[4][HF];

    const int tid = threadIdx.x;
    for (int i = tid; i < EDGE_FEATS * HF; i += 256) {
        int k = i >> 7, c = i & 127;
        WeT[c * EDGE_FEATS + k] = We[i];
    }

    const int hh = tid >> 6;
    const int k  = tid & 63;
    const int node0 = blockIdx.x * 16;
    const float scale = 0.17677669529663687f;   // 1/sqrt(32)

    for (int g = 0; g < 4; g++) {
        __syncthreads();
        for (int i = tid; i < 4 * HF; i += 256) {
            int ni = i >> 7, c = i & 127;
            int n = node0 + g * 4 + ni;
            hs[ni][c] = (n < N_NODES) ? g_h[n * HF + c] : 0.0f;
        }
        __syncthreads();

        float acc[4] = {0.f, 0.f, 0.f, 0.f};
#pragma unroll
        for (int f = 0; f < OUT_FEATS; f++) {
            float w = WeT[(hh * OUT_FEATS + f) * EDGE_FEATS + k];
#pragma unroll
            for (int ni = 0; ni < 4; ni++) acc[ni] += hs[ni][hh * OUT_FEATS + f] * w;
        }
#pragma unroll
        for (int ni = 0; ni < 4; ni++) {
            int n = node0 + g * 4 + ni;
            if (n < N_NODES)
                g_q[(n * NUM_HEADS + hh) * EDGE_FEATS + k] = acc[ni] * scale;
        }
    }
}

// ---------------------------------------------------------------------------
// CSR build: histogram -> scan (3 kernels) -> scatter
// ---------------------------------------------------------------------------
__global__ void hist_kernel(const int* __restrict__ dst) {
    int e = blockIdx.x * blockDim.x + threadIdx.x;
    if (e < N_EDGES) atomicAdd(&g_cnt[dst[e]], 1);
}

__global__ __launch_bounds__(SCAN_BLK) void scan1_kernel() {
    __shared__ int sm[SCAN_BLK];
    int t = threadIdx.x;
    int i = blockIdx.x * SCAN_BLK + t;
    sm[t] = (i < N_NODES) ? g_cnt[i] : 0;
    __syncthreads();
    for (int off = SCAN_BLK / 2; off > 0; off >>= 1) {
        if (t < off) sm[t] += sm[t + off];
        __syncthreads();
    }
    if (t == 0) g_part[blockIdx.x] = sm[0];
}

__global__ __launch_bounds__(128) void scan2_kernel() {
    __shared__ int sm[2][128];
    int t = threadIdx.x;
    int v = (t < NB_SCAN) ? g_part[t] : 0;
    int pi = 0;
    sm[0][t] = v;
    __syncthreads();
#pragma unroll
    for (int off = 1; off < 128; off <<= 1) {
        int add = (t >= off) ? sm[pi][t - off] : 0;
        sm[pi ^ 1][t] = sm[pi][t] + add;
        pi ^= 1;
        __syncthreads();
    }
    if (t < NB_SCAN) g_partx[t] = sm[pi][t] - v;   // exclusive
}

__global__ __launch_bounds__(SCAN_BLK) void scan3_kernel() {
    __shared__ int sm[2][SCAN_BLK];
    int t = threadIdx.x;
    int i = blockIdx.x * SCAN_BLK + t;
    int v = (i < N_NODES) ? g_cnt[i] : 0;
    int pi = 0;
    sm[0][t] = v;
    __syncthreads();
#pragma unroll
    for (int off = 1; off < SCAN_BLK; off <<= 1) {
        int add = (t >= off) ? sm[pi][t - off] : 0;
        sm[pi ^ 1][t] = sm[pi][t] + add;
        pi ^= 1;
        __syncthreads();
    }
    if (i < N_NODES) {
        int excl = g_partx[blockIdx.x] + sm[pi][t] - v;
        g_off[i] = excl;
        g_cur[i] = excl;
    }
    if (blockIdx.x == 0 && t == 0) g_off[N_NODES] = N_EDGES;
}

__global__ void scatter_kernel(const int* __restrict__ dst) {
    int e = blockIdx.x * blockDim.x + threadIdx.x;
    if (e < N_EDGES) {
        int pos = atomicAdd(&g_cur[dst[e]], 1);
        g_eid[pos] = e;
    }
}

// ---------------------------------------------------------------------------
// Fused: warp per dst node. Online softmax over CSR edge list.
//   score[h] = leaky( sum_k ef[e,k] * q[src,h,k] )   (q pre-scaled)
//   out[d]   = sum_e softmax(score) * h[src]
// 6-shuffle transpose-reduce leaves head (lane>>3)'s score on each lane.
// ---------------------------------------------------------------------------
__global__ __launch_bounds__(256) void fused_kernel(
    const float* __restrict__ ef, const int* __restrict__ src,
    float* __restrict__ out) {
    const int warp = (blockIdx.x * 256 + threadIdx.x) >> 5;
    if (warp >= N_NODES) return;
    const int lane = threadIdx.x & 31;
    const int d = warp;

    const int beg = __ldg(&g_off[d]);
    const int end = __ldg(&g_off[d + 1]);

    float m = -CUDART_INF_F;
    float den = 0.0f;
    float4 acc = make_float4(0.f, 0.f, 0.f, 0.f);

    const bool up = lane >= 16;
    const bool m8 = (lane & 8) != 0;

    // prefetch first edge's index chain
    int eid = 0, s = 0;
    if (beg < end) {
        eid = __ldg(&g_eid[beg]);
        s   = __ldg(&src[eid]);
    }

    for (int j = beg; j < end; j++) {
        const int eid_c = eid;
        const int s_c = s;
        const int jn = j + 1;
        if (jn < end) {                       // prefetch next index chain
            eid = __ldg(&g_eid[jn]);
            s   = __ldg(&src[eid]);
        }

        const float* efp = ef + (size_t)eid_c * EDGE_FEATS;
        const float e0 = __ldg(efp + lane);
        const float e1 = __ldg(efp + 32 + lane);

        const float* qp = g_q + (size_t)s_c * QCOLS;
        const float p0 = e0 * __ldg(qp +   0 + lane) + e1 * __ldg(qp +  32 + lane);
        const float p1 = e0 * __ldg(qp +  64 + lane) + e1 * __ldg(qp +  96 + lane);
        const float p2 = e0 * __ldg(qp + 128 + lane) + e1 * __ldg(qp + 160 + lane);
        const float p3 = e0 * __ldg(qp + 192 + lane) + e1 * __ldg(qp + 224 + lane);

        const float4 hv = *(const float4*)(g_h + (size_t)s_c * HF + lane * 4);

        // 6-shuffle transpose-reduce: lane l ends with head (l>>3)'s full sum
        float x = up ? p0 : p2;
        float a = (up ? p2 : p0) + __shfl_xor_sync(0xffffffffu, x, 16);
        float y = up ? p1 : p3;
        float b = (up ? p3 : p1) + __shfl_xor_sync(0xffffffffu, y, 16);
        float z = m8 ? a : b;
        float c = (m8 ? b : a) + __shfl_xor_sync(0xffffffffu, z, 8);
        c += __shfl_xor_sync(0xffffffffu, c, 4);
        c += __shfl_xor_sync(0xffffffffu, c, 2);
        c += __shfl_xor_sync(0xffffffffu, c, 1);

        const float sc = (c > 0.0f) ? c : 0.01f * c;       // leaky relu
        const float nm = fmaxf(m, sc);
        const float alpha = __expf(m - nm);                // 0 on first edge
        const float w = __expf(sc - nm);
        den = den * alpha + w;
        acc.x = acc.x * alpha + w * hv.x;
        acc.y = acc.y * alpha + w * hv.y;
        acc.z = acc.z * alpha + w * hv.z;
        acc.w = acc.w * alpha + w * hv.w;
        m = nm;
    }

    const float inv = (den > 0.0f) ? __frcp_rn(den) : 0.0f;
    float4 o = make_float4(acc.x * inv, acc.y * inv, acc.z * inv, acc.w * inv);
    *(float4*)(out + (size_t)d * HF + lane * 4) = o;
}

// ---------------------------------------------------------------------------
extern "C" void kernel_launch(void* const* d_in, const int* in_sizes, int n_in,
                              void* d_out, int out_size) {
    const float* node_feat = (const float*)d_in[0];
    const float* edge_feat = (const float*)d_in[1];
    const int*   src       = (const int*)d_in[2];
    const int*   dst       = (const int*)d_in[3];
    const float* W_node    = (const float*)d_in[4];
    const float* W_edge    = (const float*)d_in[5];
    float* out = (float*)d_out;

    zero_cnt_kernel<<<(N_NODES + 255) / 256, 256>>>();
    gemm_node_kernel<<<(N_NODES + 63) / 64, 256>>>(node_feat, W_node);
    make_q_kernel<<<(N_NODES + 15) / 16, 256>>>(W_edge);
    hist_kernel<<<(N_EDGES + 255) / 256, 256>>>(dst);
    scan1_kernel<<<NB_SCAN, SCAN_BLK>>>();
    scan2_kernel<<<1, 128>>>();
    scan3_kernel<<<NB_SCAN, SCAN_BLK>>>();
    scatter_kernel<<<(N_EDGES + 255) / 256, 256>>>(dst);
    fused_kernel<<<(N_NODES * 32 + 255) / 256, 256>>>(edge_feat, src, out);
}